// round 8
// baseline (speedup 1.0000x reference)
#include <cuda_runtime.h>

// DenseTNT postprocess: per-batch greedy NMS over 4096 goal candidates.
// k-th pick = argmax score among candidates not suppressed (d2 < 4.0) by
// already-picked goals. Key = (ordered_float(score) << 32) | (~idx) encodes
// stable-sort tie-break (equal score -> lower index).
//
// Lazy suppression (R6): each thread contributes only its current local-best
// candidate to the block argmax. The winner's (x,y) is PACKED INTO A u64 that
// rides the shfl chain and the 16-B warp partial -- no shared-memory goal
// mirror (whose strided STS.128 fill was 8-way bank-conflicted), no sgoal LDS
// in the round-dependent chain, no pre-round barrier.

#define B_       128
#define N_       4096
#define MODES_   6
#define THRESH2_ 4.0f
#define TPB_     512
#define PER_     8           // candidates per thread (contiguous chunk)
#define NW_      (TPB_ / 32) // 16 warps

typedef unsigned long long u64;

__device__ __forceinline__ u64 packxy(float x, float y) {
    return ((u64)__float_as_uint(y) << 32) | (u64)__float_as_uint(x);
}

__global__ __launch_bounds__(TPB_, 1)
void densetnt_nms_kernel(const float* __restrict__ scores,   // [B, N]
                         const float* __restrict__ trajs,    // [B, 60, N]
                         const float* __restrict__ goals,    // [B, 2, N]
                         float* __restrict__ out)            // [B,6,30,2] ++ [B,6]
{
    const int b    = blockIdx.x;
    const int t    = threadIdx.x;
    const int w    = t >> 5;
    const int lane = t & 31;

    __shared__ ulonglong2 red[2][NW_];    // {key, packed xy} parity double-buffer
    __shared__ u64    win_s[MODES_];
    __shared__ int    sel_s[MODES_];
    __shared__ float  ssc_s[MODES_];

    const float* sc = scores + (size_t)b * N_     + (size_t)t * PER_;
    const float* gx = goals  + (size_t)b * 2 * N_ + (size_t)t * PER_;
    const float* gy = gx + N_;
    const float* tb = trajs + (size_t)b * 60 * N_;
    float* ob = out + (size_t)b * MODES_ * 60;

    // Vectorized load of this thread's contiguous 8-candidate chunk.
    float4 s0 = ((const float4*)sc)[0], s1 = ((const float4*)sc)[1];
    float4 a0 = ((const float4*)gx)[0], a1 = ((const float4*)gx)[1];
    float4 c0 = ((const float4*)gy)[0], c1 = ((const float4*)gy)[1];

    float x[PER_]  = {a0.x, a0.y, a0.z, a0.w, a1.x, a1.y, a1.z, a1.w};
    float y[PER_]  = {c0.x, c0.y, c0.z, c0.w, c1.x, c1.y, c1.z, c1.w};
    float sv[PER_] = {s0.x, s0.y, s0.z, s0.w, s1.x, s1.y, s1.z, s1.w};

    u64 key[PER_];
#pragma unroll
    for (int j = 0; j < PER_; j++) {
        unsigned i  = (unsigned)(t * PER_ + j);
        unsigned u  = __float_as_uint(sv[j]);
        unsigned os = u ^ (0x80000000u | (unsigned)(((int)u) >> 31)); // order-preserving
        key[j] = ((u64)os << 32) | (u64)(0xFFFFFFFFu - i);
    }

    // Initial local best (no picks yet -> no validation needed).
    u64 bk = key[0]; float bx = x[0], by = y[0];
#pragma unroll
    for (int j = 1; j < PER_; j++)
        if (key[j] > bk) { bk = key[j]; bx = x[j]; by = y[j]; }
    u64 bxy = packxy(bx, by);

    float px[MODES_], py[MODES_];   // pick history (static-indexed -> registers)

    // NOTE: no barrier needed before round 0 (no shared state yet).

#pragma unroll
    for (int m = 0; m < MODES_; m++) {
        // --- warp argmax over the 32 lazy local-bests; (x,y) rides along ---
        u64 k = bk, xy = bxy;
#pragma unroll
        for (int o = 16; o > 0; o >>= 1) {
            u64 ok  = __shfl_xor_sync(0xFFFFFFFFu, k,  o);
            u64 oxy = __shfl_xor_sync(0xFFFFFFFFu, xy, o);
            if (ok > k) { k = ok; xy = oxy; }
        }
        if (lane == 0) red[m & 1][w] = make_ulonglong2(k, xy);
        __syncthreads();   // ONLY barrier this round

        // --- all threads merge the 16 warp partials (16x broadcast LDS.128) ---
        u64 win = 0ull, wxy = 0ull;
#pragma unroll
        for (int ww = 0; ww < NW_; ww++) {
            ulonglong2 p = red[m & 1][ww];
            if (p.x > win) { win = p.x; wxy = p.y; }
        }
        if (t == 0) win_s[m] = win;

        if (win != 0ull) {
            const int   widx = (int)(0xFFFFFFFFu - (unsigned)(win & 0xFFFFFFFFull));
            const float wx = __uint_as_float((unsigned)(wxy & 0xFFFFFFFFull));
            const float wy = __uint_as_float((unsigned)(wxy >> 32));
            px[m] = wx; py[m] = wy;

            // --- overlapped gather: warps 14-15 fetch mode m's trajectory ---
            if (t >= TPB_ - 64) {
                int e = t - (TPB_ - 64);
                if (e < 60) ob[m * 60 + e] = __ldg(tb + (size_t)e * N_ + widx);
            }

            // --- lazy update of local best (skipped after the final pick) ---
            if (m < MODES_ - 1) {
                float dx = bx - wx, dy = by - wy;
                bool need = (bk == win) | (bk != 0ull && dx * dx + dy * dy < THRESH2_);
                if (need) {
#pragma unroll
                    for (int j = 0; j < PER_; j++) key[j] = (key[j] == bk) ? 0ull : key[j];
                    for (;;) {   // rare path: recompute + validate vs pick history
                        u64 nk = key[0]; float nx = x[0], ny = y[0];
#pragma unroll
                        for (int j = 1; j < PER_; j++)
                            if (key[j] > nk) { nk = key[j]; nx = x[j]; ny = y[j]; }
                        if (nk == 0ull) { bk = 0ull; break; }
                        bool sup = false;
#pragma unroll
                        for (int r = 0; r < MODES_; r++) {
                            if (r <= m) {
                                float ddx = nx - px[r], ddy = ny - py[r];
                                sup |= (ddx * ddx + ddy * ddy < THRESH2_);
                            }
                        }
                        if (sup) {
#pragma unroll
                            for (int j = 0; j < PER_; j++) key[j] = (key[j] == nk) ? 0ull : key[j];
                        } else { bk = nk; bx = nx; by = ny; break; }
                    }
                    bxy = packxy(bx, by);
                }
            }
        }
        // no trailing barrier: next round writes the other parity buffer; the
        // round-(m+1) barrier bounds warp skew to one round.
    }
    __syncthreads();   // win_s[] complete

    // decode selections (empty slot -> round-0 winner = global top-1)
    if (t < MODES_) {
        u64 wv = win_s[t];
        if (wv == 0ull) wv = win_s[0];
        sel_s[t] = (int)(0xFFFFFFFFu - (unsigned)(wv & 0xFFFFFFFFull));
        unsigned os = (unsigned)(wv >> 32);
        ssc_s[t] = __uint_as_float(os ^ (0x80000000u | (unsigned)(((int)~os) >> 31)));
    }
    __syncthreads();

    // tail: only fallback modes (win==0) still need their gather
    for (int e = t; e < MODES_ * 60; e += TPB_) {
        int m = e / 60;
        if (win_s[m] == 0ull) {
            int kk = e - m * 60;
            ob[e] = __ldg(tb + (size_t)kk * N_ + sel_s[m]);
        }
    }
    if (t < MODES_) {
        out[(size_t)B_ * MODES_ * 60 + (size_t)b * MODES_ + t] = ssc_s[t];
    }
}

extern "C" void kernel_launch(void* const* d_in, const int* in_sizes, int n_in,
                              void* d_out, int out_size)
{
    const float* goals_scores = (const float*)d_in[0];  // [128, 4096]
    const float* traj_preds   = (const float*)d_in[1];  // [128, 60, 4096]
    const float* pred_goals   = (const float*)d_in[2];  // [128, 2, 4096]
    float* out = (float*)d_out;

    densetnt_nms_kernel<<<B_, TPB_>>>(goals_scores, traj_preds, pred_goals, out);
}

// round 9
// speedup vs baseline: 1.5714x; 1.5714x over previous
#include <cuda_runtime.h>

// DenseTNT postprocess: per-batch greedy NMS over 4096 goal candidates.
// k-th pick = argmax score among candidates not suppressed (d2 < 4.0) by
// already-picked goals. Key = (ordered_float(score) << 32) | (~idx) encodes
// stable-sort tie-break (equal score -> lower index).
//
// R6 structure (best so far) + SW128-swizzled sgoal mirror:
// the plain stride-64B fill put all 32 lanes of each STS.128 on 2 of 8
// 16B bank-groups (16 cyc/instr); the swizzle (XOR bits[6:4] with bits[9:7])
// spreads lanes uniformly, 4 rows per group = optimal 4 cyc/instr.
// The round-time read sgoal[widx] is a uniform broadcast: same swizzle on a
// uniform address, no extra cost (float2 stays within its 16B slot).

#define B_       128
#define N_       4096
#define MODES_   6
#define THRESH2_ 4.0f
#define TPB_     512
#define PER_     8           // candidates per thread (contiguous chunk)
#define NW_      (TPB_ / 32) // 16 warps

#define SWZ(o) ((o) ^ (((o) >> 3) & 0x70u))

typedef unsigned long long u64;

__global__ __launch_bounds__(TPB_, 1)
void densetnt_nms_kernel(const float* __restrict__ scores,   // [B, N]
                         const float* __restrict__ trajs,    // [B, 60, N]
                         const float* __restrict__ goals,    // [B, 2, N]
                         float* __restrict__ out)            // [B,6,30,2] ++ [B,6]
{
    const int b    = blockIdx.x;
    const int t    = threadIdx.x;
    const int w    = t >> 5;
    const int lane = t & 31;

    __shared__ __align__(16) char sgoal[N_ * 8];   // 32 KB swizzled goal mirror
    __shared__ u64    red[2][NW_];                 // parity double-buffer
    __shared__ u64    win_s[MODES_];
    __shared__ int    sel_s[MODES_];
    __shared__ float  ssc_s[MODES_];

    const float* sc = scores + (size_t)b * N_     + (size_t)t * PER_;
    const float* gx = goals  + (size_t)b * 2 * N_ + (size_t)t * PER_;
    const float* gy = gx + N_;
    const float* tb = trajs + (size_t)b * 60 * N_;
    float* ob = out + (size_t)b * MODES_ * 60;

    // Vectorized load of this thread's contiguous 8-candidate chunk.
    float4 s0 = ((const float4*)sc)[0], s1 = ((const float4*)sc)[1];
    float4 a0 = ((const float4*)gx)[0], a1 = ((const float4*)gx)[1];
    float4 c0 = ((const float4*)gy)[0], c1 = ((const float4*)gy)[1];

    float x[PER_]  = {a0.x, a0.y, a0.z, a0.w, a1.x, a1.y, a1.z, a1.w};
    float y[PER_]  = {c0.x, c0.y, c0.z, c0.w, c1.x, c1.y, c1.z, c1.w};
    float sv[PER_] = {s0.x, s0.y, s0.z, s0.w, s1.x, s1.y, s1.z, s1.w};

    // Swizzled goal-mirror fill: 4 STS.128, conflict-optimal.
    {
        unsigned base = (unsigned)t * 64u;
        *(float4*)(sgoal + SWZ(base      )) = make_float4(x[0], y[0], x[1], y[1]);
        *(float4*)(sgoal + SWZ(base + 16u)) = make_float4(x[2], y[2], x[3], y[3]);
        *(float4*)(sgoal + SWZ(base + 32u)) = make_float4(x[4], y[4], x[5], y[5]);
        *(float4*)(sgoal + SWZ(base + 48u)) = make_float4(x[6], y[6], x[7], y[7]);
    }

    u64 key[PER_];
#pragma unroll
    for (int j = 0; j < PER_; j++) {
        unsigned i  = (unsigned)(t * PER_ + j);
        unsigned u  = __float_as_uint(sv[j]);
        unsigned os = u ^ (0x80000000u | (unsigned)(((int)u) >> 31)); // order-preserving
        key[j] = ((u64)os << 32) | (u64)(0xFFFFFFFFu - i);
    }

    // Initial local best (no picks yet -> no validation needed).
    u64 bk = key[0]; float bx = x[0], by = y[0];
#pragma unroll
    for (int j = 1; j < PER_; j++)
        if (key[j] > bk) { bk = key[j]; bx = x[j]; by = y[j]; }

    float px[MODES_], py[MODES_];   // pick history (static-indexed -> registers)

    __syncthreads();   // sgoal ready

#pragma unroll
    for (int m = 0; m < MODES_; m++) {
        // --- warp max over the 32 lazy local-bests (5 shfl levels) ---
        u64 best = bk;
#pragma unroll
        for (int o = 16; o > 0; o >>= 1) {
            u64 v = __shfl_xor_sync(0xFFFFFFFFu, best, o);
            best = v > best ? v : best;
        }
        if (lane == 0) red[m & 1][w] = best;
        __syncthreads();   // ONLY barrier this round

        // --- all threads merge the 16 warp partials (8x LDS.128) ---
        const ulonglong2* rp = (const ulonglong2*)red[m & 1];
        u64 win = 0ull;
#pragma unroll
        for (int q = 0; q < NW_ / 2; q++) {
            ulonglong2 p = rp[q];
            u64 hi = p.x > p.y ? p.x : p.y;
            win = hi > win ? hi : win;
        }
        if (t == 0) win_s[m] = win;

        if (win != 0ull) {
            const int widx = (int)(0xFFFFFFFFu - (unsigned)(win & 0xFFFFFFFFull));
            const float2 g = *(const float2*)(sgoal + SWZ((unsigned)widx * 8u)); // broadcast
            px[m] = g.x; py[m] = g.y;

            // --- overlapped gather: warps 14-15 fetch mode m's trajectory ---
            if (t >= TPB_ - 64) {
                int e = t - (TPB_ - 64);
                if (e < 60) ob[m * 60 + e] = __ldg(tb + (size_t)e * N_ + widx);
            }

            // --- lazy update of local best (skipped after the final pick) ---
            if (m < MODES_ - 1) {
                float dx = bx - g.x, dy = by - g.y;
                bool need = (bk == win) | (bk != 0ull && dx * dx + dy * dy < THRESH2_);
                if (need) {
#pragma unroll
                    for (int j = 0; j < PER_; j++) key[j] = (key[j] == bk) ? 0ull : key[j];
                    for (;;) {   // rare path: recompute + validate vs pick history
                        u64 nk = key[0]; float nx = x[0], ny = y[0];
#pragma unroll
                        for (int j = 1; j < PER_; j++)
                            if (key[j] > nk) { nk = key[j]; nx = x[j]; ny = y[j]; }
                        if (nk == 0ull) { bk = 0ull; break; }
                        bool sup = false;
#pragma unroll
                        for (int r = 0; r < MODES_; r++) {
                            if (r <= m) {
                                float ddx = nx - px[r], ddy = ny - py[r];
                                sup |= (ddx * ddx + ddy * ddy < THRESH2_);
                            }
                        }
                        if (sup) {
#pragma unroll
                            for (int j = 0; j < PER_; j++) key[j] = (key[j] == nk) ? 0ull : key[j];
                        } else { bk = nk; bx = nx; by = ny; break; }
                    }
                }
            }
        }
        // no trailing barrier: next round writes the other parity buffer; the
        // round-(m+1) barrier bounds warp skew to one round.
    }
    __syncthreads();   // win_s[] complete

    // decode selections (empty slot -> round-0 winner = global top-1)
    if (t < MODES_) {
        u64 wv = win_s[t];
        if (wv == 0ull) wv = win_s[0];
        sel_s[t] = (int)(0xFFFFFFFFu - (unsigned)(wv & 0xFFFFFFFFull));
        unsigned os = (unsigned)(wv >> 32);
        ssc_s[t] = __uint_as_float(os ^ (0x80000000u | (unsigned)(((int)~os) >> 31)));
    }
    __syncthreads();

    // tail: only fallback modes (win==0) still need their gather
    for (int e = t; e < MODES_ * 60; e += TPB_) {
        int m = e / 60;
        if (win_s[m] == 0ull) {
            int kk = e - m * 60;
            ob[e] = __ldg(tb + (size_t)kk * N_ + sel_s[m]);
        }
    }
    if (t < MODES_) {
        out[(size_t)B_ * MODES_ * 60 + (size_t)b * MODES_ + t] = ssc_s[t];
    }
}

extern "C" void kernel_launch(void* const* d_in, const int* in_sizes, int n_in,
                              void* d_out, int out_size)
{
    const float* goals_scores = (const float*)d_in[0];  // [128, 4096]
    const float* traj_preds   = (const float*)d_in[1];  // [128, 60, 4096]
    const float* pred_goals   = (const float*)d_in[2];  // [128, 2, 4096]
    float* out = (float*)d_out;

    densetnt_nms_kernel<<<B_, TPB_>>>(goals_scores, traj_preds, pred_goals, out);
}

// round 10
// speedup vs baseline: 1.5761x; 1.0030x over previous
#include <cuda_runtime.h>

// DenseTNT postprocess: per-batch greedy NMS over 4096 goal candidates.
// k-th pick = argmax score among candidates not suppressed (d2 < 4.0) by
// already-picked goals. Key = (ordered_float(score) << 32) | (~idx) encodes
// stable-sort tie-break (equal score -> lower index).
//
// R6 structure + FIXED gather overlap: gather warps only ISSUE the LDG into
// a statically-indexed register buffer during the rounds (no dependent STG,
// so they don't stall at DRAM latency and don't drag the round barriers).
// All gathered values are stored to GMEM once, after the last round.

#define B_       128
#define N_       4096
#define MODES_   6
#define THRESH2_ 4.0f
#define TPB_     512
#define PER_     8           // candidates per thread (contiguous chunk)
#define NW_      (TPB_ / 32) // 16 warps

typedef unsigned long long u64;

__global__ __launch_bounds__(TPB_, 1)
void densetnt_nms_kernel(const float* __restrict__ scores,   // [B, N]
                         const float* __restrict__ trajs,    // [B, 60, N]
                         const float* __restrict__ goals,    // [B, 2, N]
                         float* __restrict__ out)            // [B,6,30,2] ++ [B,6]
{
    const int b    = blockIdx.x;
    const int t    = threadIdx.x;
    const int w    = t >> 5;
    const int lane = t & 31;

    __shared__ float2 sgoal[N_];          // 32 KB goal mirror (broadcast reads)
    __shared__ u64    red[2][NW_];        // parity double-buffer
    __shared__ u64    win_s[MODES_];

    const float* sc = scores + (size_t)b * N_     + (size_t)t * PER_;
    const float* gx = goals  + (size_t)b * 2 * N_ + (size_t)t * PER_;
    const float* gy = gx + N_;
    const float* tb = trajs + (size_t)b * 60 * N_;
    float* ob = out + (size_t)b * MODES_ * 60;

    // Vectorized load of this thread's contiguous 8-candidate chunk.
    float4 s0 = ((const float4*)sc)[0], s1 = ((const float4*)sc)[1];
    float4 a0 = ((const float4*)gx)[0], a1 = ((const float4*)gx)[1];
    float4 c0 = ((const float4*)gy)[0], c1 = ((const float4*)gy)[1];

    float x[PER_]  = {a0.x, a0.y, a0.z, a0.w, a1.x, a1.y, a1.z, a1.w};
    float y[PER_]  = {c0.x, c0.y, c0.z, c0.w, c1.x, c1.y, c1.z, c1.w};
    float sv[PER_] = {s0.x, s0.y, s0.z, s0.w, s1.x, s1.y, s1.z, s1.w};

    // Fill goal mirror with 4 STS.128.
    {
        float4* dst = (float4*)(sgoal + (size_t)t * PER_);
        dst[0] = make_float4(x[0], y[0], x[1], y[1]);
        dst[1] = make_float4(x[2], y[2], x[3], y[3]);
        dst[2] = make_float4(x[4], y[4], x[5], y[5]);
        dst[3] = make_float4(x[6], y[6], x[7], y[7]);
    }

    u64 key[PER_];
#pragma unroll
    for (int j = 0; j < PER_; j++) {
        unsigned i  = (unsigned)(t * PER_ + j);
        unsigned u  = __float_as_uint(sv[j]);
        unsigned os = u ^ (0x80000000u | (unsigned)(((int)u) >> 31)); // order-preserving
        key[j] = ((u64)os << 32) | (u64)(0xFFFFFFFFu - i);
    }

    // Initial local best (no picks yet -> no validation needed).
    u64 bk = key[0]; float bx = x[0], by = y[0];
#pragma unroll
    for (int j = 1; j < PER_; j++)
        if (key[j] > bk) { bk = key[j]; bx = x[j]; by = y[j]; }

    float px[MODES_], py[MODES_];   // pick history (static-indexed -> registers)
    float gbuf[MODES_];             // gather buffer (gather warps only)
    unsigned wmask = 0;             // bit m set <=> round m had a winner

    const bool is_gather = (t >= TPB_ - 64) && (t - (TPB_ - 64) < 60);
    const int  ge        = t - (TPB_ - 64);   // gather element (valid if is_gather)

    __syncthreads();   // sgoal ready

#pragma unroll
    for (int m = 0; m < MODES_; m++) {
        // --- warp max over the 32 lazy local-bests (5 shfl levels) ---
        u64 best = bk;
#pragma unroll
        for (int o = 16; o > 0; o >>= 1) {
            u64 v = __shfl_xor_sync(0xFFFFFFFFu, best, o);
            best = v > best ? v : best;
        }
        if (lane == 0) red[m & 1][w] = best;
        __syncthreads();   // ONLY barrier this round

        // --- all threads merge the 16 warp partials (8x LDS.128) ---
        const ulonglong2* rp = (const ulonglong2*)red[m & 1];
        u64 win = 0ull;
#pragma unroll
        for (int q = 0; q < NW_ / 2; q++) {
            ulonglong2 p = rp[q];
            u64 hi = p.x > p.y ? p.x : p.y;
            win = hi > win ? hi : win;
        }
        if (t == 0) win_s[m] = win;

        if (win != 0ull) {
            wmask |= 1u << m;
            const int widx = (int)(0xFFFFFFFFu - (unsigned)(win & 0xFFFFFFFFull));
            const float2 g = sgoal[widx];      // broadcast read
            px[m] = g.x; py[m] = g.y;

            // --- gather: ISSUE ONLY (value consumed after the loop) ---
            if (is_gather) gbuf[m] = __ldg(tb + (size_t)ge * N_ + widx);

            // --- lazy update of local best (skipped after the final pick) ---
            if (m < MODES_ - 1) {
                float dx = bx - g.x, dy = by - g.y;
                bool need = (bk == win) | (bk != 0ull && dx * dx + dy * dy < THRESH2_);
                if (need) {
#pragma unroll
                    for (int j = 0; j < PER_; j++) key[j] = (key[j] == bk) ? 0ull : key[j];
                    for (;;) {   // rare path: recompute + validate vs pick history
                        u64 nk = key[0]; float nx = x[0], ny = y[0];
#pragma unroll
                        for (int j = 1; j < PER_; j++)
                            if (key[j] > nk) { nk = key[j]; nx = x[j]; ny = y[j]; }
                        if (nk == 0ull) { bk = 0ull; break; }
                        bool sup = false;
#pragma unroll
                        for (int r = 0; r < MODES_; r++) {
                            if (r <= m) {
                                float ddx = nx - px[r], ddy = ny - py[r];
                                sup |= (ddx * ddx + ddy * ddy < THRESH2_);
                            }
                        }
                        if (sup) {
#pragma unroll
                            for (int j = 0; j < PER_; j++) key[j] = (key[j] == nk) ? 0ull : key[j];
                        } else { bk = nk; bx = nx; by = ny; break; }
                    }
                }
            }
        }
        // no trailing barrier: next round writes the other parity buffer; the
        // round-(m+1) barrier bounds warp skew to one round.
    }

    // --- gather epilogue: 6 STGs per gather thread; fallback modes reuse
    //     round-0's value (round 0 always has a winner: all keys nonzero) ---
    if (is_gather) {
#pragma unroll
        for (int m = 0; m < MODES_; m++) {
            ob[m * 60 + ge] = (wmask & (1u << m)) ? gbuf[m] : gbuf[0];
        }
    }

    __syncthreads();   // win_s[] complete

    // scores (empty slot -> round-0 winner = global top-1)
    if (t < MODES_) {
        u64 wv = win_s[t];
        if (wv == 0ull) wv = win_s[0];
        unsigned os = (unsigned)(wv >> 32);
        out[(size_t)B_ * MODES_ * 60 + (size_t)b * MODES_ + t] =
            __uint_as_float(os ^ (0x80000000u | (unsigned)(((int)~os) >> 31)));
    }
}

extern "C" void kernel_launch(void* const* d_in, const int* in_sizes, int n_in,
                              void* d_out, int out_size)
{
    const float* goals_scores = (const float*)d_in[0];  // [128, 4096]
    const float* traj_preds   = (const float*)d_in[1];  // [128, 60, 4096]
    const float* pred_goals   = (const float*)d_in[2];  // [128, 2, 4096]
    float* out = (float*)d_out;

    densetnt_nms_kernel<<<B_, TPB_>>>(goals_scores, traj_preds, pred_goals, out);
}